// round 9
// baseline (speedup 1.0000x reference)
#include <cuda_runtime.h>
#include <cuda_fp16.h>
#include <cstdint>

#define NN   4096
#define FIN  128
#define FOUT 64
#define NH   8
#define CT   1024
#define SLOPE 0.2f
#define BS_H 144   // halves per B smem row: 128 data + 16 pad (word-stride 72 ≡ 8 mod 32)

// ---------------- scratch (device globals; no allocations) ----------------
__device__ float    g_W[FIN * CT];
__device__ float    g_hs[NN * CT];            // [n][1024]: 0..511 h per head, 512..1023 skip
__device__ __half   g_hH[NH * FOUT * NN];     // [h][o][j], f16, j 16-groups frag-permuted
__device__ float    g_ssrc[NH * NN];
__device__ float    g_sdst[NH * NN];
__device__ unsigned g_maskT[(NN / 32) * NN];  // [word w][i] transposed adjacency bitmask
__device__ float    g_attn[NH * NN * FOUT];

__device__ __forceinline__ uint32_t smem_u32(const void* p) {
    uint32_t a;
    asm("{ .reg .u64 t; cvta.to.shared.u64 t, %1; cvt.u32.u64 %0, t; }" : "=r"(a) : "l"(p));
    return a;
}

// ---------------- pack proj + skip_w^T into one [128][1024] weight --------
__global__ void k_pack_w(const float* __restrict__ proj, const float* __restrict__ skw) {
    int idx = blockIdx.x * 256 + threadIdx.x;
    int k = idx >> 10, c = idx & 1023;
    float v;
    if (c < 512) v = proj[(c >> 6) * (FIN * FOUT) + k * FOUT + (c & 63)];
    else         v = skw[(c - 512) * FIN + k];
    g_W[idx] = v;
}

// ---------------- adjacency bitmask (transposed: [word][i]) ---------------
// each warp produces 4 mask words (4 strided coalesced reads + 4 ballots)
__global__ void k_mask(const float* __restrict__ topo) {
    int wt = blockIdx.x * 8 + (threadIdx.x >> 5);   // 0..131071
    int lane = threadIdx.x & 31;
    int i = wt >> 5, w4 = (wt & 31) * 4;
    const float* row = topo + (size_t)i * NN + w4 * 32;
    unsigned b0 = __ballot_sync(0xffffffffu, row[lane]      > -1e8f);
    unsigned b1 = __ballot_sync(0xffffffffu, row[32 + lane] > -1e8f);
    unsigned b2 = __ballot_sync(0xffffffffu, row[64 + lane] > -1e8f);
    unsigned b3 = __ballot_sync(0xffffffffu, row[96 + lane] > -1e8f);
    if (lane < 4) {
        unsigned bb = (lane == 0) ? b0 : (lane == 1) ? b1 : (lane == 2) ? b2 : b3;
        g_maskT[(w4 + lane) * NN + i] = bb;
    }
}

// ---------------- GEMM: g_hs = x[4096x128] @ g_W[128x1024] ----------------
__global__ void __launch_bounds__(256) k_gemm(const float* __restrict__ x) {
    __shared__ float sX[64][68];
    __shared__ float sB[64][64];
    int tid = threadIdx.x;
    int bm = blockIdx.x, bn = blockIdx.y;
    int tr = tid >> 4, tc = tid & 15;
    float4 acc0 = make_float4(0.f,0.f,0.f,0.f);
    float4 acc1 = acc0, acc2 = acc0, acc3 = acc0;
    for (int kk = 0; kk < 2; kk++) {
        __syncthreads();
        #pragma unroll
        for (int it = 0; it < 4; it++) {
            int idx = tid + it * 256;
            int row = idx >> 4, k4 = idx & 15;
            float4 v = *(const float4*)(x + (bm * 64 + row) * FIN + kk * 64 + k4 * 4);
            *(float4*)(&sX[row][k4 * 4]) = v;
        }
        #pragma unroll
        for (int it = 0; it < 4; it++) {
            int idx = tid + it * 256;
            int k = idx >> 4, c4 = idx & 15;
            float4 v = *(const float4*)(g_W + (kk * 64 + k) * CT + bn * 64 + c4 * 4);
            *(float4*)(&sB[k][c4 * 4]) = v;
        }
        __syncthreads();
        #pragma unroll 8
        for (int k = 0; k < 64; k++) {
            float4 b = *(const float4*)(&sB[k][tc * 4]);
            float a0 = sX[tr * 4 + 0][k];
            float a1 = sX[tr * 4 + 1][k];
            float a2 = sX[tr * 4 + 2][k];
            float a3 = sX[tr * 4 + 3][k];
            acc0.x += a0 * b.x; acc0.y += a0 * b.y; acc0.z += a0 * b.z; acc0.w += a0 * b.w;
            acc1.x += a1 * b.x; acc1.y += a1 * b.y; acc1.z += a1 * b.z; acc1.w += a1 * b.w;
            acc2.x += a2 * b.x; acc2.y += a2 * b.y; acc2.z += a2 * b.z; acc2.w += a2 * b.w;
            acc3.x += a3 * b.x; acc3.y += a3 * b.y; acc3.z += a3 * b.z; acc3.w += a3 * b.w;
        }
    }
    float* dst = g_hs + (bm * 64 + tr * 4) * CT + bn * 64 + tc * 4;
    *(float4*)(dst + 0 * CT) = acc0;
    *(float4*)(dst + 1 * CT) = acc1;
    *(float4*)(dst + 2 * CT) = acc2;
    *(float4*)(dst + 3 * CT) = acc3;
}

// ---------------- s_src / s_dst dot products ------------------------------
__global__ void k_svec(const float* __restrict__ wsrc, const float* __restrict__ wdst) {
    int gw = blockIdx.x * 8 + (threadIdx.x >> 5);
    int lane = threadIdx.x & 31;
    int h = gw >> 12, n = gw & 4095;
    float2 hv = *(const float2*)(g_hs + n * CT + h * 64 + lane * 2);
    float2 a  = *(const float2*)(wsrc + h * 64 + lane * 2);
    float2 b  = *(const float2*)(wdst + h * 64 + lane * 2);
    float ss = hv.x * a.x + hv.y * a.y;
    float sd = hv.x * b.x + hv.y * b.y;
    #pragma unroll
    for (int o = 16; o > 0; o >>= 1) {
        ss += __shfl_xor_sync(0xffffffffu, ss, o);
        sd += __shfl_xor_sync(0xffffffffu, sd, o);
    }
    if (lane == 0) { g_ssrc[h * NN + n] = ss; g_sdst[h * NN + n] = sd; }
}

// fragment-gather permutation within each 16-j group:
// physical slot of logical k: k<8 -> (k>>1)*4 + (k&1) ; k>=8 -> ((k-8)>>1)*4 + 2 + (k&1)
__device__ __forceinline__ int fragperm(int k) {
    return (k < 8) ? ((k >> 1) * 4 + (k & 1))
                   : (((k - 8) >> 1) * 4 + 2 + (k & 1));
}

// ---------------- transpose h to f16 (frag-permuted j): g_hH[h][o][j'] ----
__global__ void k_transp() {
    __shared__ float s[32][33];
    int h = blockIdx.z, ot = blockIdx.y, jt = blockIdx.x;
    int x = threadIdx.x, y = threadIdx.y;   // block (32, 8)
    #pragma unroll
    for (int r = 0; r < 4; r++) {
        int j = jt * 32 + y + r * 8;
        s[y + r * 8][x] = g_hs[j * CT + h * 64 + ot * 32 + x];
    }
    __syncthreads();
    int jp = jt * 32 + (x >> 4) * 16 + fragperm(x & 15);
    #pragma unroll
    for (int r = 0; r < 4; r++) {
        int o = ot * 32 + y + r * 8;
        g_hH[(h * 64 + o) * NN + jp] = __float2half_rn(s[x][y + r * 8]);
    }
}

// ---------------- B tile loader: g_hH[64 o][128 j'] -> smem (stride 144) --
__device__ __forceinline__ void load_btile(const __half* __restrict__ hH, int jt,
                                           uint32_t bufb, int tid) {
    #pragma unroll
    for (int c = 0; c < 8; c++) {
        int idx = tid + c * 128;             // 1024 chunks: 64 rows x 16 x 16B
        int o = idx >> 4, ck = idx & 15;
        uint32_t dst = bufb + (uint32_t)(o * (BS_H * 2) + ck * 16);
        const __half* src = hH + o * NN + jt * 128 + ck * 8;
        asm volatile("cp.async.cg.shared.global [%0], [%1], 16;"
                     :: "r"(dst), "l"(src) : "memory");
    }
}

// ---------------- masked exp --------------------------------------------
__device__ __forceinline__ float pexp(float ssrc, float sd, unsigned m, int sh,
                                      float& rs) {
    float v = ssrc + sd;
    v = fmaxf(v, SLOPE * v);
    float p = ((m >> sh) & 1u) ? __expf(v) : 0.f;
    rs += p;
    return p;
}

__device__ __forceinline__ uint32_t pack_h2(float lo, float hi) {
    uint32_t u;
    asm("cvt.rn.f16x2.f32 %0, %1, %2;" : "=r"(u) : "f"(hi), "f"(lo));
    return u;
}

// ---------------- main attention: P-gen + P@h via mma.sync f16 ------------
// grid (64 i-tiles, 8 heads), block 128 = 4 warps; warp owns 16 i-rows.
__global__ void __launch_bounds__(128, 5) k_attn() {
    __shared__ __half   sB[2][64 * BS_H];   // 2 x 18432 B
    __shared__ float    s_sdst[128];
    __shared__ unsigned smask[64 * 4];      // [row r][word q]

    int tid = threadIdx.x, lane = tid & 31, wid = tid >> 5;
    int g = lane >> 2, t = lane & 3;
    int head = blockIdx.y, ibase = blockIdx.x * 64;
    int r1 = wid * 16 + g, r2 = r1 + 8;

    float ssr1 = g_ssrc[head * NN + ibase + r1];
    float ssr2 = g_ssrc[head * NN + ibase + r2];
    const __half* hH = g_hH + (size_t)head * (FOUT * NN);
    uint32_t sb0 = smem_u32(sB);

    float acc[8][4];
    #pragma unroll
    for (int nt = 0; nt < 8; nt++)
        acc[nt][0] = acc[nt][1] = acc[nt][2] = acc[nt][3] = 0.f;
    float rs1 = 0.f, rs2 = 0.f;

    load_btile(hH, 0, sb0, tid);
    asm volatile("cp.async.commit_group;" ::: "memory");

    for (int jt = 0; jt < 32; jt++) {
        __syncthreads();                    // prior compute done: stage + buf reuse safe
        s_sdst[tid] = g_sdst[head * NN + jt * 128 + tid];
        #pragma unroll
        for (int s = tid; s < 256; s += 128)
            smask[(s & 63) * 4 + (s >> 6)] =
                g_maskT[(jt * 4 + (s >> 6)) * NN + ibase + (s & 63)];
        if (jt < 31)
            load_btile(hH, jt + 1, sb0 + (uint32_t)(((jt + 1) & 1) * (64 * BS_H * 2)), tid);
        asm volatile("cp.async.commit_group;" ::: "memory");
        asm volatile("cp.async.wait_group 1;" ::: "memory");   // tile jt resident
        __syncthreads();

        const __half* buf = sB[jt & 1];

        #pragma unroll
        for (int c = 0; c < 8; c++) {
            int kb = c * 16;
            float2 sdA = *(const float2*)(s_sdst + kb + 2 * t);      // j = 2t, 2t+1
            float2 sdB = *(const float2*)(s_sdst + kb + 2 * t + 8);  // j = 2t+8, 2t+9
            unsigned m1 = smask[r1 * 4 + (c >> 1)];
            unsigned m2 = smask[r2 * 4 + (c >> 1)];
            int sb = (c & 1) * 16 + 2 * t;

            float p10 = pexp(ssr1, sdA.x, m1, sb,     rs1);
            float p11 = pexp(ssr1, sdA.y, m1, sb + 1, rs1);
            float p18 = pexp(ssr1, sdB.x, m1, sb + 8, rs1);
            float p19 = pexp(ssr1, sdB.y, m1, sb + 9, rs1);
            float p20 = pexp(ssr2, sdA.x, m2, sb,     rs2);
            float p21 = pexp(ssr2, sdA.y, m2, sb + 1, rs2);
            float p28 = pexp(ssr2, sdB.x, m2, sb + 8, rs2);
            float p29 = pexp(ssr2, sdB.y, m2, sb + 9, rs2);

            uint32_t a0 = pack_h2(p10, p11);   // (r1, k=2t,2t+1)
            uint32_t a1 = pack_h2(p20, p21);   // (r2, k low)
            uint32_t a2 = pack_h2(p18, p19);   // (r1, k high)
            uint32_t a3 = pack_h2(p28, p29);   // (r2, k high)

            // B: frag-permuted rows -> one LDS.64 yields (2t,2t+1,2t+8,2t+9)
            const __half* bp = buf + g * BS_H + kb + 4 * t;
            #pragma unroll
            for (int nt = 0; nt < 8; nt++) {
                uint2 bv = *(const uint2*)(bp + nt * (8 * BS_H));
                asm volatile(
                    "mma.sync.aligned.m16n8k16.row.col.f32.f16.f16.f32 "
                    "{%0,%1,%2,%3}, {%4,%5,%6,%7}, {%8,%9}, {%0,%1,%2,%3};"
                    : "+f"(acc[nt][0]), "+f"(acc[nt][1]),
                      "+f"(acc[nt][2]), "+f"(acc[nt][3])
                    : "r"(a0), "r"(a1), "r"(a2), "r"(a3), "r"(bv.x), "r"(bv.y));
            }
        }
    }

    // row-sum reduce over the 4 lanes sharing each row, normalize, store
    rs1 += __shfl_xor_sync(0xffffffffu, rs1, 1);
    rs1 += __shfl_xor_sync(0xffffffffu, rs1, 2);
    rs2 += __shfl_xor_sync(0xffffffffu, rs2, 1);
    rs2 += __shfl_xor_sync(0xffffffffu, rs2, 2);
    float inv1 = 1.0f / rs1, inv2 = 1.0f / rs2;

    float* o1 = g_attn + (size_t)(head * NN + ibase + r1) * FOUT + 2 * t;
    float* o2 = g_attn + (size_t)(head * NN + ibase + r2) * FOUT + 2 * t;
    #pragma unroll
    for (int nt = 0; nt < 8; nt++) {
        float2 v1; v1.x = acc[nt][0] * inv1; v1.y = acc[nt][1] * inv1;
        float2 v2; v2.x = acc[nt][2] * inv2; v2.y = acc[nt][3] * inv2;
        *(float2*)(o1 + nt * 8) = v1;
        *(float2*)(o2 + nt * 8) = v2;
    }
}

// ---------------- finalize: mean over heads (+ skip), LeakyReLU -----------
__global__ void k_final(float* __restrict__ out) {
    int idx = blockIdx.x * 256 + threadIdx.x;
    int i = idx >> 6, o = idx & 63;
    float s = 0.f;
    #pragma unroll
    for (int h = 0; h < NH; h++)
        s += g_attn[(h * NN + i) * FOUT + o] + g_hs[i * CT + 512 + h * 64 + o];
    s *= 0.125f;
    out[idx] = fmaxf(s, SLOPE * s);
}

// ---------------- launch ---------------------------------------------------
extern "C" void kernel_launch(void* const* d_in, const int* in_sizes, int n_in,
                              void* d_out, int out_size) {
    const float* x    = (const float*)d_in[0];   // [4096,128]
    const float* topo = (const float*)d_in[1];   // [4096,4096]
    const float* proj = (const float*)d_in[2];   // [8,128,64]
    const float* wsrc = (const float*)d_in[3];   // [8,64]
    const float* wdst = (const float*)d_in[4];   // [8,64]
    const float* skw  = (const float*)d_in[5];   // [512,128]
    float* out = (float*)d_out;                  // [4096,64]

    k_pack_w<<<512, 256>>>(proj, skw);
    k_mask<<<16384, 256>>>(topo);
    k_gemm<<<dim3(64, 16), 256>>>(x);
    k_svec<<<4096, 256>>>(wsrc, wdst);
    k_transp<<<dim3(128, 2, 8), dim3(32, 8)>>>();
    k_attn<<<dim3(64, 8), 128>>>();
    k_final<<<1024, 256>>>(out);
}

// round 10
// speedup vs baseline: 1.5089x; 1.5089x over previous
#include <cuda_runtime.h>
#include <cuda_fp16.h>
#include <cstdint>

#define NN   4096
#define FIN  128
#define FOUT 64
#define NH   8
#define CT   1024
#define SLOPE 0.2f
#define BS_H 144   // halves per B smem row: 128 data + 16 pad (word-stride 72 ≡ 8 mod 32)

// ---------------- scratch (device globals; no allocations) ----------------
__device__ float    g_W[FIN * CT];
__device__ float    g_hs[NN * CT];            // [n][1024]: 0..511 h per head, 512..1023 skip
__device__ __half   g_hH[NH * FOUT * NN];     // [h][o][j], f16, j 16-groups frag-permuted
__device__ float    g_ssrc[NH * NN];
__device__ float    g_sdst[NH * NN];
__device__ unsigned g_maskT[(NN / 32) * NN];  // [word w][i] transposed adjacency bitmask
__device__ float    g_attn[NH * NN * FOUT];

__device__ __forceinline__ uint32_t smem_u32(const void* p) {
    uint32_t a;
    asm("{ .reg .u64 t; cvta.to.shared.u64 t, %1; cvt.u32.u64 %0, t; }" : "=r"(a) : "l"(p));
    return a;
}

// ---------------- pack proj + skip_w^T into one [128][1024] weight --------
__global__ void k_pack_w(const float* __restrict__ proj, const float* __restrict__ skw) {
    int idx = blockIdx.x * 256 + threadIdx.x;
    int k = idx >> 10, c = idx & 1023;
    float v;
    if (c < 512) v = proj[(c >> 6) * (FIN * FOUT) + k * FOUT + (c & 63)];
    else         v = skw[(c - 512) * FIN + k];
    g_W[idx] = v;
}

// ---------------- adjacency bitmask (transposed: [word][i]) ---------------
__global__ void k_mask(const float* __restrict__ topo) {
    int wt = blockIdx.x * 8 + (threadIdx.x >> 5);   // 0..131071
    int lane = threadIdx.x & 31;
    int i = wt >> 5, w4 = (wt & 31) * 4;
    const float* row = topo + (size_t)i * NN + w4 * 32;
    unsigned b0 = __ballot_sync(0xffffffffu, row[lane]      > -1e8f);
    unsigned b1 = __ballot_sync(0xffffffffu, row[32 + lane] > -1e8f);
    unsigned b2 = __ballot_sync(0xffffffffu, row[64 + lane] > -1e8f);
    unsigned b3 = __ballot_sync(0xffffffffu, row[96 + lane] > -1e8f);
    if (lane < 4) {
        unsigned bb = (lane == 0) ? b0 : (lane == 1) ? b1 : (lane == 2) ? b2 : b3;
        g_maskT[(w4 + lane) * NN + i] = bb;
    }
}

// ---------------- GEMM: g_hs = x[4096x128] @ g_W[128x1024] ----------------
__global__ void __launch_bounds__(256) k_gemm(const float* __restrict__ x) {
    __shared__ float sX[64][68];
    __shared__ float sB[64][64];
    int tid = threadIdx.x;
    int bm = blockIdx.x, bn = blockIdx.y;
    int tr = tid >> 4, tc = tid & 15;
    float4 acc0 = make_float4(0.f,0.f,0.f,0.f);
    float4 acc1 = acc0, acc2 = acc0, acc3 = acc0;
    for (int kk = 0; kk < 2; kk++) {
        __syncthreads();
        #pragma unroll
        for (int it = 0; it < 4; it++) {
            int idx = tid + it * 256;
            int row = idx >> 4, k4 = idx & 15;
            float4 v = *(const float4*)(x + (bm * 64 + row) * FIN + kk * 64 + k4 * 4);
            *(float4*)(&sX[row][k4 * 4]) = v;
        }
        #pragma unroll
        for (int it = 0; it < 4; it++) {
            int idx = tid + it * 256;
            int k = idx >> 4, c4 = idx & 15;
            float4 v = *(const float4*)(g_W + (kk * 64 + k) * CT + bn * 64 + c4 * 4);
            *(float4*)(&sB[k][c4 * 4]) = v;
        }
        __syncthreads();
        #pragma unroll 8
        for (int k = 0; k < 64; k++) {
            float4 b = *(const float4*)(&sB[k][tc * 4]);
            float a0 = sX[tr * 4 + 0][k];
            float a1 = sX[tr * 4 + 1][k];
            float a2 = sX[tr * 4 + 2][k];
            float a3 = sX[tr * 4 + 3][k];
            acc0.x += a0 * b.x; acc0.y += a0 * b.y; acc0.z += a0 * b.z; acc0.w += a0 * b.w;
            acc1.x += a1 * b.x; acc1.y += a1 * b.y; acc1.z += a1 * b.z; acc1.w += a1 * b.w;
            acc2.x += a2 * b.x; acc2.y += a2 * b.y; acc2.z += a2 * b.z; acc2.w += a2 * b.w;
            acc3.x += a3 * b.x; acc3.y += a3 * b.y; acc3.z += a3 * b.z; acc3.w += a3 * b.w;
        }
    }
    float* dst = g_hs + (bm * 64 + tr * 4) * CT + bn * 64 + tc * 4;
    *(float4*)(dst + 0 * CT) = acc0;
    *(float4*)(dst + 1 * CT) = acc1;
    *(float4*)(dst + 2 * CT) = acc2;
    *(float4*)(dst + 3 * CT) = acc3;
}

// ---------------- s_src / s_dst dot products ------------------------------
__global__ void k_svec(const float* __restrict__ wsrc, const float* __restrict__ wdst) {
    int gw = blockIdx.x * 8 + (threadIdx.x >> 5);
    int lane = threadIdx.x & 31;
    int h = gw >> 12, n = gw & 4095;
    float2 hv = *(const float2*)(g_hs + n * CT + h * 64 + lane * 2);
    float2 a  = *(const float2*)(wsrc + h * 64 + lane * 2);
    float2 b  = *(const float2*)(wdst + h * 64 + lane * 2);
    float ss = hv.x * a.x + hv.y * a.y;
    float sd = hv.x * b.x + hv.y * b.y;
    #pragma unroll
    for (int o = 16; o > 0; o >>= 1) {
        ss += __shfl_xor_sync(0xffffffffu, ss, o);
        sd += __shfl_xor_sync(0xffffffffu, sd, o);
    }
    if (lane == 0) { g_ssrc[h * NN + n] = ss; g_sdst[h * NN + n] = sd; }
}

// fragment-gather permutation within each 16-j group:
// physical slot of logical k: k<8 -> (k>>1)*4 + (k&1) ; k>=8 -> ((k-8)>>1)*4 + 2 + (k&1)
__device__ __forceinline__ int fragperm(int k) {
    return (k < 8) ? ((k >> 1) * 4 + (k & 1))
                   : (((k - 8) >> 1) * 4 + 2 + (k & 1));
}

// ---------------- transpose h to f16 (frag-permuted j): g_hH[h][o][j'] ----
__global__ void k_transp() {
    __shared__ float s[32][33];
    int h = blockIdx.z, ot = blockIdx.y, jt = blockIdx.x;
    int x = threadIdx.x, y = threadIdx.y;   // block (32, 8)
    #pragma unroll
    for (int r = 0; r < 4; r++) {
        int j = jt * 32 + y + r * 8;
        s[y + r * 8][x] = g_hs[j * CT + h * 64 + ot * 32 + x];
    }
    __syncthreads();
    int jp = jt * 32 + (x >> 4) * 16 + fragperm(x & 15);
    #pragma unroll
    for (int r = 0; r < 4; r++) {
        int o = ot * 32 + y + r * 8;
        g_hH[(h * 64 + o) * NN + jp] = __float2half_rn(s[x][y + r * 8]);
    }
}

// ---------------- B tile loader: g_hH[64 o][128 j'] -> smem (stride 144) --
__device__ __forceinline__ void load_btile(const __half* __restrict__ hH, int jt,
                                           uint32_t bufb, int tid) {
    #pragma unroll
    for (int c = 0; c < 4; c++) {
        int idx = tid + c * 256;             // 1024 chunks: 64 rows x 16 x 16B
        int o = idx >> 4, ck = idx & 15;
        uint32_t dst = bufb + (uint32_t)(o * (BS_H * 2) + ck * 16);
        const __half* src = hH + o * NN + jt * 128 + ck * 8;
        asm volatile("cp.async.cg.shared.global [%0], [%1], 16;"
                     :: "r"(dst), "l"(src) : "memory");
    }
}

// ---------------- masked exp ----------------------------------------------
__device__ __forceinline__ float pexp(float ssrc, float sd, unsigned m, int sh,
                                      float& rs) {
    float v = ssrc + sd;
    v = fmaxf(v, SLOPE * v);
    float p = ((m >> sh) & 1u) ? __expf(v) : 0.f;
    rs += p;
    return p;
}

__device__ __forceinline__ uint32_t pack_h2(float lo, float hi) {
    uint32_t u;
    asm("cvt.rn.f16x2.f32 %0, %1, %2;" : "=r"(u) : "f"(hi), "f"(lo));
    return u;
}

// ---------------- main attention: P-gen + P@h via mma.sync f16 ------------
// grid (32 i-tiles, 8 heads), block 256 = 8 warps; warp owns 16 i-rows (R8 geometry).
__global__ void __launch_bounds__(256, 3) k_attn() {
    __shared__ __half   sB[2][64 * BS_H];   // 2 x 18432 B
    __shared__ float    s_sdst[128];
    __shared__ unsigned smask[128 * 4];     // [row r][word q]

    int tid = threadIdx.x, lane = tid & 31, wid = tid >> 5;
    int g = lane >> 2, t = lane & 3;
    int head = blockIdx.y, ibase = blockIdx.x * 128;
    int r1 = wid * 16 + g, r2 = r1 + 8;

    float ssr1 = g_ssrc[head * NN + ibase + r1];
    float ssr2 = g_ssrc[head * NN + ibase + r2];
    const __half* hH = g_hH + (size_t)head * (FOUT * NN);
    uint32_t sb0 = smem_u32(sB);

    float acc[8][4];
    #pragma unroll
    for (int nt = 0; nt < 8; nt++)
        acc[nt][0] = acc[nt][1] = acc[nt][2] = acc[nt][3] = 0.f;
    float rs1 = 0.f, rs2 = 0.f;

    load_btile(hH, 0, sb0, tid);
    asm volatile("cp.async.commit_group;" ::: "memory");

    for (int jt = 0; jt < 32; jt++) {
        __syncthreads();                    // prior compute done: stage + buf reuse safe
        if (tid < 128) s_sdst[tid] = g_sdst[head * NN + jt * 128 + tid];
        #pragma unroll
        for (int s = tid; s < 512; s += 256)
            smask[(s & 127) * 4 + (s >> 7)] =
                g_maskT[(jt * 4 + (s >> 7)) * NN + ibase + (s & 127)];
        if (jt < 31)
            load_btile(hH, jt + 1, sb0 + (uint32_t)(((jt + 1) & 1) * (64 * BS_H * 2)), tid);
        asm volatile("cp.async.commit_group;" ::: "memory");
        asm volatile("cp.async.wait_group 1;" ::: "memory");   // tile jt resident
        __syncthreads();

        const __half* buf = sB[jt & 1];

        #pragma unroll
        for (int c = 0; c < 8; c++) {
            int kb = c * 16;
            float2 sdA = *(const float2*)(s_sdst + kb + 2 * t);      // j = 2t, 2t+1
            float2 sdB = *(const float2*)(s_sdst + kb + 2 * t + 8);  // j = 2t+8, 2t+9
            unsigned m1 = smask[r1 * 4 + (c >> 1)];
            unsigned m2 = smask[r2 * 4 + (c >> 1)];
            int sb = (c & 1) * 16 + 2 * t;

            float p10 = pexp(ssr1, sdA.x, m1, sb,     rs1);
            float p11 = pexp(ssr1, sdA.y, m1, sb + 1, rs1);
            float p18 = pexp(ssr1, sdB.x, m1, sb + 8, rs1);
            float p19 = pexp(ssr1, sdB.y, m1, sb + 9, rs1);
            float p20 = pexp(ssr2, sdA.x, m2, sb,     rs2);
            float p21 = pexp(ssr2, sdA.y, m2, sb + 1, rs2);
            float p28 = pexp(ssr2, sdB.x, m2, sb + 8, rs2);
            float p29 = pexp(ssr2, sdB.y, m2, sb + 9, rs2);

            uint32_t a0 = pack_h2(p10, p11);   // (r1, k=2t,2t+1)
            uint32_t a1 = pack_h2(p20, p21);   // (r2, k low)
            uint32_t a2 = pack_h2(p18, p19);   // (r1, k high)
            uint32_t a3 = pack_h2(p28, p29);   // (r2, k high)

            // B: frag-permuted rows -> one LDS.64 yields (2t,2t+1,2t+8,2t+9)
            const __half* bp = buf + g * BS_H + kb + 4 * t;
            #pragma unroll
            for (int nt = 0; nt < 8; nt++) {
                uint2 bv = *(const uint2*)(bp + nt * (8 * BS_H));
                asm volatile(
                    "mma.sync.aligned.m16n8k16.row.col.f32.f16.f16.f32 "
                    "{%0,%1,%2,%3}, {%4,%5,%6,%7}, {%8,%9}, {%0,%1,%2,%3};"
                    : "+f"(acc[nt][0]), "+f"(acc[nt][1]),
                      "+f"(acc[nt][2]), "+f"(acc[nt][3])
                    : "r"(a0), "r"(a1), "r"(a2), "r"(a3), "r"(bv.x), "r"(bv.y));
            }
        }
    }

    // row-sum reduce over the 4 lanes sharing each row, normalize, store
    rs1 += __shfl_xor_sync(0xffffffffu, rs1, 1);
    rs1 += __shfl_xor_sync(0xffffffffu, rs1, 2);
    rs2 += __shfl_xor_sync(0xffffffffu, rs2, 1);
    rs2 += __shfl_xor_sync(0xffffffffu, rs2, 2);
    float inv1 = 1.0f / rs1, inv2 = 1.0f / rs2;

    float* o1 = g_attn + (size_t)(head * NN + ibase + r1) * FOUT + 2 * t;
    float* o2 = g_attn + (size_t)(head * NN + ibase + r2) * FOUT + 2 * t;
    #pragma unroll
    for (int nt = 0; nt < 8; nt++) {
        float2 v1; v1.x = acc[nt][0] * inv1; v1.y = acc[nt][1] * inv1;
        float2 v2; v2.x = acc[nt][2] * inv2; v2.y = acc[nt][3] * inv2;
        *(float2*)(o1 + nt * 8) = v1;
        *(float2*)(o2 + nt * 8) = v2;
    }
}

// ---------------- finalize: mean over heads (+ skip), LeakyReLU -----------
__global__ void k_final(float* __restrict__ out) {
    int idx = blockIdx.x * 256 + threadIdx.x;
    int i = idx >> 6, o = idx & 63;
    float s = 0.f;
    #pragma unroll
    for (int h = 0; h < NH; h++)
        s += g_attn[(h * NN + i) * FOUT + o] + g_hs[i * CT + 512 + h * 64 + o];
    s *= 0.125f;
    out[idx] = fmaxf(s, SLOPE * s);
}

// ---------------- launch ---------------------------------------------------
extern "C" void kernel_launch(void* const* d_in, const int* in_sizes, int n_in,
                              void* d_out, int out_size) {
    const float* x    = (const float*)d_in[0];   // [4096,128]
    const float* topo = (const float*)d_in[1];   // [4096,4096]
    const float* proj = (const float*)d_in[2];   // [8,128,64]
    const float* wsrc = (const float*)d_in[3];   // [8,64]
    const float* wdst = (const float*)d_in[4];   // [8,64]
    const float* skw  = (const float*)d_in[5];   // [512,128]
    float* out = (float*)d_out;                  // [4096,64]

    k_pack_w<<<512, 256>>>(proj, skw);
    k_mask<<<16384, 256>>>(topo);
    k_gemm<<<dim3(64, 16), 256>>>(x);
    k_svec<<<4096, 256>>>(wsrc, wdst);
    k_transp<<<dim3(128, 2, 8), dim3(32, 8)>>>();
    k_attn<<<dim3(32, 8), 256>>>();
    k_final<<<1024, 256>>>(out);
}

// round 11
// speedup vs baseline: 1.8961x; 1.2566x over previous
#include <cuda_runtime.h>
#include <cuda_fp16.h>
#include <cstdint>

#define NN   4096
#define FIN  128
#define FOUT 64
#define NH   8
#define CT   1024
#define SLOPE 0.2f
#define BS_H 144   // halves per B smem row: 128 data + 16 pad (word-stride 72 ≡ 8 mod 32)
#define LOG2E 1.4426950408889634f

// ---------------- scratch (device globals; no allocations) ----------------
__device__ float    g_W[FIN * CT];
__device__ float    g_hs[NN * CT];            // [n][1024]: 0..511 h per head, 512..1023 skip
__device__ __half   g_hH[NH * FOUT * NN];     // [h][o][j], f16, j 16-groups frag-permuted
__device__ float    g_ssrc[NH * NN];          // pre-scaled by log2(e)
__device__ float    g_sdst[NH * NN];          // pre-scaled by log2(e)
__device__ unsigned g_maskT[(NN / 32) * NN];  // [word w][i] transposed adjacency bitmask
__device__ float    g_attn[NH * NN * FOUT];

__device__ __forceinline__ uint32_t smem_u32(const void* p) {
    uint32_t a;
    asm("{ .reg .u64 t; cvta.to.shared.u64 t, %1; cvt.u32.u64 %0, t; }" : "=r"(a) : "l"(p));
    return a;
}

// ---------------- pack proj + skip_w^T into one [128][1024] weight --------
__global__ void k_pack_w(const float* __restrict__ proj, const float* __restrict__ skw) {
    int idx = blockIdx.x * 256 + threadIdx.x;
    int k = idx >> 10, c = idx & 1023;
    float v;
    if (c < 512) v = proj[(c >> 6) * (FIN * FOUT) + k * FOUT + (c & 63)];
    else         v = skw[(c - 512) * FIN + k];
    g_W[idx] = v;
}

// ---------------- adjacency bitmask (transposed: [word][i]) ---------------
__global__ void k_mask(const float* __restrict__ topo) {
    int wt = blockIdx.x * 8 + (threadIdx.x >> 5);   // 0..131071
    int lane = threadIdx.x & 31;
    int i = wt >> 5, w4 = (wt & 31) * 4;
    const float* row = topo + (size_t)i * NN + w4 * 32;
    unsigned b0 = __ballot_sync(0xffffffffu, row[lane]      > -1e8f);
    unsigned b1 = __ballot_sync(0xffffffffu, row[32 + lane] > -1e8f);
    unsigned b2 = __ballot_sync(0xffffffffu, row[64 + lane] > -1e8f);
    unsigned b3 = __ballot_sync(0xffffffffu, row[96 + lane] > -1e8f);
    if (lane < 4) {
        unsigned bb = (lane == 0) ? b0 : (lane == 1) ? b1 : (lane == 2) ? b2 : b3;
        g_maskT[(w4 + lane) * NN + i] = bb;
    }
}

// ---------------- GEMM: g_hs = x[4096x128] @ g_W[128x1024] ----------------
__global__ void __launch_bounds__(256) k_gemm(const float* __restrict__ x) {
    __shared__ float sX[64][68];
    __shared__ float sB[64][64];
    int tid = threadIdx.x;
    int bm = blockIdx.x, bn = blockIdx.y;
    int tr = tid >> 4, tc = tid & 15;
    float4 acc0 = make_float4(0.f,0.f,0.f,0.f);
    float4 acc1 = acc0, acc2 = acc0, acc3 = acc0;
    for (int kk = 0; kk < 2; kk++) {
        __syncthreads();
        #pragma unroll
        for (int it = 0; it < 4; it++) {
            int idx = tid + it * 256;
            int row = idx >> 4, k4 = idx & 15;
            float4 v = *(const float4*)(x + (bm * 64 + row) * FIN + kk * 64 + k4 * 4);
            *(float4*)(&sX[row][k4 * 4]) = v;
        }
        #pragma unroll
        for (int it = 0; it < 4; it++) {
            int idx = tid + it * 256;
            int k = idx >> 4, c4 = idx & 15;
            float4 v = *(const float4*)(g_W + (kk * 64 + k) * CT + bn * 64 + c4 * 4);
            *(float4*)(&sB[k][c4 * 4]) = v;
        }
        __syncthreads();
        #pragma unroll 8
        for (int k = 0; k < 64; k++) {
            float4 b = *(const float4*)(&sB[k][tc * 4]);
            float a0 = sX[tr * 4 + 0][k];
            float a1 = sX[tr * 4 + 1][k];
            float a2 = sX[tr * 4 + 2][k];
            float a3 = sX[tr * 4 + 3][k];
            acc0.x += a0 * b.x; acc0.y += a0 * b.y; acc0.z += a0 * b.z; acc0.w += a0 * b.w;
            acc1.x += a1 * b.x; acc1.y += a1 * b.y; acc1.z += a1 * b.z; acc1.w += a1 * b.w;
            acc2.x += a2 * b.x; acc2.y += a2 * b.y; acc2.z += a2 * b.z; acc2.w += a2 * b.w;
            acc3.x += a3 * b.x; acc3.y += a3 * b.y; acc3.z += a3 * b.z; acc3.w += a3 * b.w;
        }
    }
    float* dst = g_hs + (bm * 64 + tr * 4) * CT + bn * 64 + tc * 4;
    *(float4*)(dst + 0 * CT) = acc0;
    *(float4*)(dst + 1 * CT) = acc1;
    *(float4*)(dst + 2 * CT) = acc2;
    *(float4*)(dst + 3 * CT) = acc3;
}

// ---------------- s_src / s_dst dot products (pre-scaled by log2e) --------
__global__ void k_svec(const float* __restrict__ wsrc, const float* __restrict__ wdst) {
    int gw = blockIdx.x * 8 + (threadIdx.x >> 5);
    int lane = threadIdx.x & 31;
    int h = gw >> 12, n = gw & 4095;
    float2 hv = *(const float2*)(g_hs + n * CT + h * 64 + lane * 2);
    float2 a  = *(const float2*)(wsrc + h * 64 + lane * 2);
    float2 b  = *(const float2*)(wdst + h * 64 + lane * 2);
    float ss = hv.x * a.x + hv.y * a.y;
    float sd = hv.x * b.x + hv.y * b.y;
    #pragma unroll
    for (int o = 16; o > 0; o >>= 1) {
        ss += __shfl_xor_sync(0xffffffffu, ss, o);
        sd += __shfl_xor_sync(0xffffffffu, sd, o);
    }
    if (lane == 0) {
        g_ssrc[h * NN + n] = ss * LOG2E;
        g_sdst[h * NN + n] = sd * LOG2E;
    }
}

// fragment-gather permutation within each 16-j group:
__device__ __forceinline__ int fragperm(int k) {
    return (k < 8) ? ((k >> 1) * 4 + (k & 1))
                   : (((k - 8) >> 1) * 4 + 2 + (k & 1));
}

// ---------------- transpose h to f16 (frag-permuted j): g_hH[h][o][j'] ----
__global__ void k_transp() {
    __shared__ float s[32][33];
    int h = blockIdx.z, ot = blockIdx.y, jt = blockIdx.x;
    int x = threadIdx.x, y = threadIdx.y;   // block (32, 8)
    #pragma unroll
    for (int r = 0; r < 4; r++) {
        int j = jt * 32 + y + r * 8;
        s[y + r * 8][x] = g_hs[j * CT + h * 64 + ot * 32 + x];
    }
    __syncthreads();
    int jp = jt * 32 + (x >> 4) * 16 + fragperm(x & 15);
    #pragma unroll
    for (int r = 0; r < 4; r++) {
        int o = ot * 32 + y + r * 8;
        g_hH[(h * 64 + o) * NN + jp] = __float2half_rn(s[x][y + r * 8]);
    }
}

// ---------------- B tile loader: g_hH[64 o][128 j'] -> smem (stride 144) --
__device__ __forceinline__ void load_btile(const __half* __restrict__ hH, int jt,
                                           uint32_t bufb, int tid) {
    #pragma unroll
    for (int c = 0; c < 4; c++) {
        int idx = tid + c * 256;             // 1024 chunks: 64 rows x 16 x 16B
        int o = idx >> 4, ck = idx & 15;
        uint32_t dst = bufb + (uint32_t)(o * (BS_H * 2) + ck * 16);
        const __half* src = hH + o * NN + jt * 128 + ck * 8;
        asm volatile("cp.async.cg.shared.global [%0], [%1], 16;"
                     :: "r"(dst), "l"(src) : "memory");
    }
}

// ---------------- masked exp2 (inputs pre-scaled by log2e) ----------------
__device__ __forceinline__ float pexp(float ssrc, float sd, unsigned m, int sh,
                                      float& rs) {
    float v = ssrc + sd;
    v = fmaxf(v, SLOPE * v);
    float e;
    asm("ex2.approx.f32 %0, %1;" : "=f"(e) : "f"(v));
    float p = ((m >> sh) & 1u) ? e : 0.f;
    rs += p;
    return p;
}

__device__ __forceinline__ uint32_t pack_h2(float lo, float hi) {
    uint32_t u;
    asm("cvt.rn.f16x2.f32 %0, %1, %2;" : "=r"(u) : "f"(hi), "f"(lo));
    return u;
}

// ---------------- main attention: P-gen + P@h via mma.sync f16 ------------
// grid (32 i-tiles, 8 heads), block 256 = 8 warps; warp owns 16 i-rows.
// Single __syncthreads per j-tile; all staging double-buffered + reg-prefetched.
__global__ void __launch_bounds__(256, 3) k_attn() {
    __shared__ __half   sB[2][64 * BS_H];   // 2 x 18432 B
    __shared__ float    s_sdst[2][128];
    __shared__ unsigned smask[2][128 * 4];  // [row r][word q]

    int tid = threadIdx.x, lane = tid & 31, wid = tid >> 5;
    int g = lane >> 2, t = lane & 3;
    int head = blockIdx.y, ibase = blockIdx.x * 128;
    int r1 = wid * 16 + g, r2 = r1 + 8;
    int srow = tid & 127, sq = tid >> 7;    // staging coords: row, word-pair selector

    float ssr1 = g_ssrc[head * NN + ibase + r1];
    float ssr2 = g_ssrc[head * NN + ibase + r2];
    const __half* hH = g_hH + (size_t)head * (FOUT * NN);
    uint32_t sb0 = smem_u32(sB);

    float acc[8][4];
    #pragma unroll
    for (int nt = 0; nt < 8; nt++)
        acc[nt][0] = acc[nt][1] = acc[nt][2] = acc[nt][3] = 0.f;
    float rs1 = 0.f, rs2 = 0.f;

    // prologue: stage jt=0 (regs -> smem buf 0), start B(0)
    float    sd_r = (tid < 128) ? g_sdst[head * NN + tid] : 0.f;
    unsigned mA = g_maskT[sq * NN + ibase + srow];
    unsigned mB = g_maskT[(2 + sq) * NN + ibase + srow];
    if (tid < 128) s_sdst[0][tid] = sd_r;
    smask[0][srow * 4 + sq]     = mA;
    smask[0][srow * 4 + 2 + sq] = mB;
    load_btile(hH, 0, sb0, tid);
    asm volatile("cp.async.commit_group;" ::: "memory");

    for (int jt = 0; jt < 32; jt++) {
        // early gmem prefetch for jt+1 (latency hidden under compute below)
        if (jt < 31) {
            if (tid < 128) sd_r = g_sdst[head * NN + (jt + 1) * 128 + tid];
            mA = g_maskT[((jt + 1) * 4 + sq) * NN + ibase + srow];
            mB = g_maskT[((jt + 1) * 4 + 2 + sq) * NN + ibase + srow];
        }

        // B(jt) complete (issued a full compute-phase ago), then one barrier:
        // closes compute jt-1 everywhere + makes STS(jt)/B(jt) visible.
        asm volatile("cp.async.wait_group 0;" ::: "memory");
        __syncthreads();

        // start B(jt+1): safe, everyone is past compute jt-1 (which read buf (jt+1)&1)
        if (jt < 31) {
            load_btile(hH, jt + 1, sb0 + (uint32_t)(((jt + 1) & 1) * (64 * BS_H * 2)), tid);
            asm volatile("cp.async.commit_group;" ::: "memory");
        }

        const __half*   buf = sB[jt & 1];
        const float*    sds = s_sdst[jt & 1];
        const unsigned* msk = smask[jt & 1];

        #pragma unroll
        for (int c = 0; c < 8; c++) {
            int kb = c * 16;
            float2 sdA = *(const float2*)(sds + kb + 2 * t);      // j = 2t, 2t+1
            float2 sdB = *(const float2*)(sds + kb + 2 * t + 8);  // j = 2t+8, 2t+9
            unsigned m1 = msk[r1 * 4 + (c >> 1)];
            unsigned m2 = msk[r2 * 4 + (c >> 1)];
            int sb = (c & 1) * 16 + 2 * t;

            float p10 = pexp(ssr1, sdA.x, m1, sb,     rs1);
            float p11 = pexp(ssr1, sdA.y, m1, sb + 1, rs1);
            float p18 = pexp(ssr1, sdB.x, m1, sb + 8, rs1);
            float p19 = pexp(ssr1, sdB.y, m1, sb + 9, rs1);
            float p20 = pexp(ssr2, sdA.x, m2, sb,     rs2);
            float p21 = pexp(ssr2, sdA.y, m2, sb + 1, rs2);
            float p28 = pexp(ssr2, sdB.x, m2, sb + 8, rs2);
            float p29 = pexp(ssr2, sdB.y, m2, sb + 9, rs2);

            uint32_t a0 = pack_h2(p10, p11);
            uint32_t a1 = pack_h2(p20, p21);
            uint32_t a2 = pack_h2(p18, p19);
            uint32_t a3 = pack_h2(p28, p29);

            const __half* bp = buf + g * BS_H + kb + 4 * t;
            #pragma unroll
            for (int nt = 0; nt < 8; nt++) {
                uint2 bv = *(const uint2*)(bp + nt * (8 * BS_H));
                asm volatile(
                    "mma.sync.aligned.m16n8k16.row.col.f32.f16.f16.f32 "
                    "{%0,%1,%2,%3}, {%4,%5,%6,%7}, {%8,%9}, {%0,%1,%2,%3};"
                    : "+f"(acc[nt][0]), "+f"(acc[nt][1]),
                      "+f"(acc[nt][2]), "+f"(acc[nt][3])
                    : "r"(a0), "r"(a1), "r"(a2), "r"(a3), "r"(bv.x), "r"(bv.y));
            }
        }

        // stage jt+1 into the other buffer (reads of it ended before this
        // iteration's barrier; made visible by next iteration's barrier)
        if (jt < 31) {
            if (tid < 128) s_sdst[(jt + 1) & 1][tid] = sd_r;
            smask[(jt + 1) & 1][srow * 4 + sq]     = mA;
            smask[(jt + 1) & 1][srow * 4 + 2 + sq] = mB;
        }
    }

    // row-sum reduce over the 4 lanes sharing each row, normalize, store
    rs1 += __shfl_xor_sync(0xffffffffu, rs1, 1);
    rs1 += __shfl_xor_sync(0xffffffffu, rs1, 2);
    rs2 += __shfl_xor_sync(0xffffffffu, rs2, 1);
    rs2 += __shfl_xor_sync(0xffffffffu, rs2, 2);
    float inv1 = 1.0f / rs1, inv2 = 1.0f / rs2;

    float* o1 = g_attn + (size_t)(head * NN + ibase + r1) * FOUT + 2 * t;
    float* o2 = g_attn + (size_t)(head * NN + ibase + r2) * FOUT + 2 * t;
    #pragma unroll
    for (int nt = 0; nt < 8; nt++) {
        float2 v1; v1.x = acc[nt][0] * inv1; v1.y = acc[nt][1] * inv1;
        float2 v2; v2.x = acc[nt][2] * inv2; v2.y = acc[nt][3] * inv2;
        *(float2*)(o1 + nt * 8) = v1;
        *(float2*)(o2 + nt * 8) = v2;
    }
}

// ---------------- finalize: mean over heads (+ skip), LeakyReLU -----------
__global__ void k_final(float* __restrict__ out) {
    int idx = blockIdx.x * 256 + threadIdx.x;
    int i = idx >> 6, o = idx & 63;
    float s = 0.f;
    #pragma unroll
    for (int h = 0; h < NH; h++)
        s += g_attn[(h * NN + i) * FOUT + o] + g_hs[i * CT + 512 + h * 64 + o];
    s *= 0.125f;
    out[idx] = fmaxf(s, SLOPE * s);
}

// ---------------- launch ---------------------------------------------------
extern "C" void kernel_launch(void* const* d_in, const int* in_sizes, int n_in,
                              void* d_out, int out_size) {
    const float* x    = (const float*)d_in[0];   // [4096,128]
    const float* topo = (const float*)d_in[1];   // [4096,4096]
    const float* proj = (const float*)d_in[2];   // [8,128,64]
    const float* wsrc = (const float*)d_in[3];   // [8,64]
    const float* wdst = (const float*)d_in[4];   // [8,64]
    const float* skw  = (const float*)d_in[5];   // [512,128]
    float* out = (float*)d_out;                  // [4096,64]

    k_pack_w<<<512, 256>>>(proj, skw);
    k_mask<<<16384, 256>>>(topo);
    k_gemm<<<dim3(64, 16), 256>>>(x);
    k_svec<<<4096, 256>>>(wsrc, wdst);
    k_transp<<<dim3(128, 2, 8), dim3(32, 8)>>>();
    k_attn<<<dim3(32, 8), 256>>>();
    k_final<<<1024, 256>>>(out);
}

// round 12
// speedup vs baseline: 2.3654x; 1.2475x over previous
#include <cuda_runtime.h>
#include <cuda_fp16.h>
#include <cstdint>

#define NN   4096
#define FIN  128
#define FOUT 64
#define NH   8
#define CT   1024
#define SLOPE 0.2f
#define BS_H 144   // halves per B smem row: 128 data + 16 pad (word-stride 72 ≡ 8 mod 32)
#define LOG2E 1.4426950408889634f

// ---------------- scratch (device globals; no allocations) ----------------
__device__ float    g_Wt[CT * FIN];           // packed weights [1024 c][128 k], tf32-rounded
__device__ float    g_hs[NN * CT];            // [n][1024]: 0..511 h per head, 512..1023 skip
__device__ __half   g_hH[NH * FOUT * NN];     // [h][o][j], f16, j 16-groups frag-permuted
__device__ float    g_ssrc[NH * NN];          // pre-scaled by log2(e)
__device__ float    g_sdst[NH * NN];          // pre-scaled by log2(e)
__device__ unsigned g_maskT[(NN / 32) * NN];  // [word w][i] transposed adjacency bitmask
__device__ float    g_attn[NH * NN * FOUT];

__device__ __forceinline__ uint32_t smem_u32(const void* p) {
    uint32_t a;
    asm("{ .reg .u64 t; cvta.to.shared.u64 t, %1; cvt.u32.u64 %0, t; }" : "=r"(a) : "l"(p));
    return a;
}

__device__ __forceinline__ float rndtf32(float v) {
    uint32_t u;
    asm("cvt.rna.tf32.f32 %0, %1;" : "=r"(u) : "f"(v));
    return __uint_as_float(u);
}

// ---------------- pack proj + skip_w^T (transposed, tf32-rounded) ---------
__global__ void k_pack_w(const float* __restrict__ proj, const float* __restrict__ skw) {
    int idx = blockIdx.x * 256 + threadIdx.x;   // 0..131071
    int c = idx >> 7, k = idx & 127;
    float v = (c < 512) ? proj[(c >> 6) * (FIN * FOUT) + k * FOUT + (c & 63)]
                        : skw[(c - 512) * FIN + k];
    g_Wt[idx] = rndtf32(v);
}

// ---------------- adjacency bitmask (transposed: [word][i]) ---------------
__global__ void k_mask(const float* __restrict__ topo) {
    int wt = blockIdx.x * 8 + (threadIdx.x >> 5);   // 0..131071
    int lane = threadIdx.x & 31;
    int i = wt >> 5, w4 = (wt & 31) * 4;
    const float* row = topo + (size_t)i * NN + w4 * 32;
    unsigned b0 = __ballot_sync(0xffffffffu, row[lane]      > -1e8f);
    unsigned b1 = __ballot_sync(0xffffffffu, row[32 + lane] > -1e8f);
    unsigned b2 = __ballot_sync(0xffffffffu, row[64 + lane] > -1e8f);
    unsigned b3 = __ballot_sync(0xffffffffu, row[96 + lane] > -1e8f);
    if (lane < 4) {
        unsigned bb = (lane == 0) ? b0 : (lane == 1) ? b1 : (lane == 2) ? b2 : b3;
        g_maskT[(w4 + lane) * NN + i] = bb;
    }
}

// ---------------- GEMM (tf32 tensor cores): g_hs = x @ Wt^T ---------------
// grid (32 m-tiles, 8 n-tiles), 256 thr / 8 warps; warp tile 64m x 32n.
__global__ void __launch_bounds__(256) k_gemm(const float* __restrict__ x) {
    __shared__ float sA[128][36];   // m x (32k + 4 pad): frag loads conflict-free
    __shared__ float sB[128][36];   // n x (32k + 4 pad)
    int tid = threadIdx.x, lane = tid & 31, wid = tid >> 5;
    int g = lane >> 2, t = lane & 3;
    int bm = blockIdx.x, bn = blockIdx.y;
    int wm = (wid & 1) * 64, wn = (wid >> 1) * 32;

    float acc[4][4][4];
    #pragma unroll
    for (int mf = 0; mf < 4; mf++)
        #pragma unroll
        for (int nf = 0; nf < 4; nf++)
            acc[mf][nf][0] = acc[mf][nf][1] = acc[mf][nf][2] = acc[mf][nf][3] = 0.f;

    for (int kc = 0; kc < 4; kc++) {
        __syncthreads();
        #pragma unroll
        for (int it = 0; it < 4; it++) {
            int idx = tid + it * 256;           // 1024: 128 rows x 8 float4
            int r = idx >> 3, kq = idx & 7;
            float4 v = *(const float4*)(x + (size_t)(bm * 128 + r) * FIN + kc * 32 + kq * 4);
            sA[r][kq * 4 + 0] = rndtf32(v.x);
            sA[r][kq * 4 + 1] = rndtf32(v.y);
            sA[r][kq * 4 + 2] = rndtf32(v.z);
            sA[r][kq * 4 + 3] = rndtf32(v.w);
            float4 w = *(const float4*)(g_Wt + (size_t)(bn * 128 + r) * FIN + kc * 32 + kq * 4);
            *(float4*)(&sB[r][kq * 4]) = w;     // pre-rounded
        }
        __syncthreads();
        #pragma unroll
        for (int ks = 0; ks < 4; ks++) {
            int kk = ks * 8;
            uint32_t a[4][4], b[4][2];
            #pragma unroll
            for (int mf = 0; mf < 4; mf++) {
                a[mf][0] = __float_as_uint(sA[wm + mf * 16 + g][kk + t]);
                a[mf][1] = __float_as_uint(sA[wm + mf * 16 + 8 + g][kk + t]);
                a[mf][2] = __float_as_uint(sA[wm + mf * 16 + g][kk + 4 + t]);
                a[mf][3] = __float_as_uint(sA[wm + mf * 16 + 8 + g][kk + 4 + t]);
            }
            #pragma unroll
            for (int nf = 0; nf < 4; nf++) {
                b[nf][0] = __float_as_uint(sB[wn + nf * 8 + g][kk + t]);
                b[nf][1] = __float_as_uint(sB[wn + nf * 8 + g][kk + 4 + t]);
            }
            #pragma unroll
            for (int mf = 0; mf < 4; mf++)
                #pragma unroll
                for (int nf = 0; nf < 4; nf++)
                    asm volatile(
                        "mma.sync.aligned.m16n8k8.row.col.f32.tf32.tf32.f32 "
                        "{%0,%1,%2,%3}, {%4,%5,%6,%7}, {%8,%9}, {%0,%1,%2,%3};"
                        : "+f"(acc[mf][nf][0]), "+f"(acc[mf][nf][1]),
                          "+f"(acc[mf][nf][2]), "+f"(acc[mf][nf][3])
                        : "r"(a[mf][0]), "r"(a[mf][1]), "r"(a[mf][2]), "r"(a[mf][3]),
                          "r"(b[nf][0]), "r"(b[nf][1]));
        }
    }

    #pragma unroll
    for (int mf = 0; mf < 4; mf++)
        #pragma unroll
        for (int nf = 0; nf < 4; nf++) {
            int m = bm * 128 + wm + mf * 16;
            int col = bn * 128 + wn + nf * 8 + 2 * t;
            float2 v0; v0.x = acc[mf][nf][0]; v0.y = acc[mf][nf][1];
            float2 v1; v1.x = acc[mf][nf][2]; v1.y = acc[mf][nf][3];
            *(float2*)(g_hs + (size_t)(m + g) * CT + col)     = v0;
            *(float2*)(g_hs + (size_t)(m + 8 + g) * CT + col) = v1;
        }
}

// ---------------- s_src / s_dst dot products (pre-scaled by log2e) --------
__global__ void k_svec(const float* __restrict__ wsrc, const float* __restrict__ wdst) {
    int gw = blockIdx.x * 8 + (threadIdx.x >> 5);
    int lane = threadIdx.x & 31;
    int h = gw >> 12, n = gw & 4095;
    float2 hv = *(const float2*)(g_hs + n * CT + h * 64 + lane * 2);
    float2 a  = *(const float2*)(wsrc + h * 64 + lane * 2);
    float2 b  = *(const float2*)(wdst + h * 64 + lane * 2);
    float ss = hv.x * a.x + hv.y * a.y;
    float sd = hv.x * b.x + hv.y * b.y;
    #pragma unroll
    for (int o = 16; o > 0; o >>= 1) {
        ss += __shfl_xor_sync(0xffffffffu, ss, o);
        sd += __shfl_xor_sync(0xffffffffu, sd, o);
    }
    if (lane == 0) {
        g_ssrc[h * NN + n] = ss * LOG2E;
        g_sdst[h * NN + n] = sd * LOG2E;
    }
}

// fragment-gather permutation within each 16-j group:
__device__ __forceinline__ int fragperm(int k) {
    return (k < 8) ? ((k >> 1) * 4 + (k & 1))
                   : (((k - 8) >> 1) * 4 + 2 + (k & 1));
}

// ---------------- transpose h to f16 (frag-permuted j): g_hH[h][o][j'] ----
__global__ void k_transp() {
    __shared__ float s[32][33];
    int h = blockIdx.z, ot = blockIdx.y, jt = blockIdx.x;
    int x = threadIdx.x, y = threadIdx.y;   // block (32, 8)
    #pragma unroll
    for (int r = 0; r < 4; r++) {
        int j = jt * 32 + y + r * 8;
        s[y + r * 8][x] = g_hs[j * CT + h * 64 + ot * 32 + x];
    }
    __syncthreads();
    int jp = jt * 32 + (x >> 4) * 16 + fragperm(x & 15);
    #pragma unroll
    for (int r = 0; r < 4; r++) {
        int o = ot * 32 + y + r * 8;
        g_hH[(h * 64 + o) * NN + jp] = __float2half_rn(s[x][y + r * 8]);
    }
}

// ---------------- B tile loader: g_hH[64 o][128 j'] -> smem (stride 144) --
__device__ __forceinline__ void load_btile(const __half* __restrict__ hH, int jt,
                                           uint32_t bufb, int tid) {
    #pragma unroll
    for (int c = 0; c < 4; c++) {
        int idx = tid + c * 256;             // 1024 chunks: 64 rows x 16 x 16B
        int o = idx >> 4, ck = idx & 15;
        uint32_t dst = bufb + (uint32_t)(o * (BS_H * 2) + ck * 16);
        const __half* src = hH + o * NN + jt * 128 + ck * 8;
        asm volatile("cp.async.cg.shared.global [%0], [%1], 16;"
                     :: "r"(dst), "l"(src) : "memory");
    }
}

__device__ __forceinline__ uint32_t pack_h2(float lo, float hi) {
    uint32_t u;
    asm("cvt.rn.f16x2.f32 %0, %1, %2;" : "=r"(u) : "f"(hi), "f"(lo));
    return u;
}

// masked leaky + paired f16x2 exp2 (inputs pre-scaled by log2e)
__device__ __forceinline__ uint32_t pgen2(float ssrc, float2 sd, unsigned m, int sh) {
    float v0 = ssrc + sd.x;
    float v1 = ssrc + sd.y;
    v0 = fmaxf(v0, SLOPE * v0);
    v1 = fmaxf(v1, SLOPE * v1);
    v0 = ((m >> sh) & 1u) ? v0 : -1e5f;          // -> f16 -inf/sat -> exp2 = 0
    v1 = ((m >> (sh + 1)) & 1u) ? v1 : -1e5f;
    uint32_t pk = pack_h2(v0, v1);
    uint32_t e;
    asm("ex2.approx.f16x2 %0, %1;" : "=r"(e) : "r"(pk));
    return e;
}

// ---------------- main attention: P-gen + P@h via mma.sync f16 ------------
// grid (32 i-tiles, 8 heads), block 256 = 8 warps; warp owns 16 i-rows.
// Row-sums accumulated by an extra mma against an all-ones B fragment.
__global__ void __launch_bounds__(256, 3) k_attn() {
    __shared__ __half   sB[2][64 * BS_H];   // 2 x 18432 B
    __shared__ float    s_sdst[2][128];
    __shared__ unsigned smask[2][128 * 4];  // [row r][word q]

    int tid = threadIdx.x, lane = tid & 31, wid = tid >> 5;
    int g = lane >> 2, t = lane & 3;
    int head = blockIdx.y, ibase = blockIdx.x * 128;
    int r1 = wid * 16 + g, r2 = r1 + 8;
    int srow = tid & 127, sq = tid >> 7;

    float ssr1 = g_ssrc[head * NN + ibase + r1];
    float ssr2 = g_ssrc[head * NN + ibase + r2];
    const __half* hH = g_hH + (size_t)head * (FOUT * NN);
    uint32_t sb0 = smem_u32(sB);
    const uint32_t ONES = 0x3C003C00u;      // (1.0h, 1.0h)

    float acc[8][4], accR[4];
    #pragma unroll
    for (int nt = 0; nt < 8; nt++)
        acc[nt][0] = acc[nt][1] = acc[nt][2] = acc[nt][3] = 0.f;
    accR[0] = accR[1] = accR[2] = accR[3] = 0.f;

    // prologue: stage jt=0 (regs -> smem buf 0), start B(0)
    float    sd_r = (tid < 128) ? g_sdst[head * NN + tid] : 0.f;
    unsigned mA = g_maskT[sq * NN + ibase + srow];
    unsigned mB = g_maskT[(2 + sq) * NN + ibase + srow];
    if (tid < 128) s_sdst[0][tid] = sd_r;
    smask[0][srow * 4 + sq]     = mA;
    smask[0][srow * 4 + 2 + sq] = mB;
    load_btile(hH, 0, sb0, tid);
    asm volatile("cp.async.commit_group;" ::: "memory");

    for (int jt = 0; jt < 32; jt++) {
        // early gmem prefetch for jt+1 (latency hidden under compute below)
        if (jt < 31) {
            if (tid < 128) sd_r = g_sdst[head * NN + (jt + 1) * 128 + tid];
            mA = g_maskT[((jt + 1) * 4 + sq) * NN + ibase + srow];
            mB = g_maskT[((jt + 1) * 4 + 2 + sq) * NN + ibase + srow];
        }

        asm volatile("cp.async.wait_group 0;" ::: "memory");
        __syncthreads();

        if (jt < 31) {
            load_btile(hH, jt + 1, sb0 + (uint32_t)(((jt + 1) & 1) * (64 * BS_H * 2)), tid);
            asm volatile("cp.async.commit_group;" ::: "memory");
        }

        const __half*   buf = sB[jt & 1];
        const float*    sds = s_sdst[jt & 1];
        const unsigned* msk = smask[jt & 1];

        #pragma unroll
        for (int c = 0; c < 8; c++) {
            int kb = c * 16;
            float2 sdA = *(const float2*)(sds + kb + 2 * t);      // j = 2t, 2t+1
            float2 sdB = *(const float2*)(sds + kb + 2 * t + 8);  // j = 2t+8, 2t+9
            unsigned m1 = msk[r1 * 4 + (c >> 1)];
            unsigned m2 = msk[r2 * 4 + (c >> 1)];
            int sb = (c & 1) * 16 + 2 * t;

            uint32_t a0 = pgen2(ssr1, sdA, m1, sb);        // (r1, k low pair)
            uint32_t a1 = pgen2(ssr2, sdA, m2, sb);        // (r2, k low pair)
            uint32_t a2 = pgen2(ssr1, sdB, m1, sb + 8);    // (r1, k high pair)
            uint32_t a3 = pgen2(ssr2, sdB, m2, sb + 8);    // (r2, k high pair)

            const __half* bp = buf + g * BS_H + kb + 4 * t;
            #pragma unroll
            for (int nt = 0; nt < 8; nt++) {
                uint2 bv = *(const uint2*)(bp + nt * (8 * BS_H));
                asm volatile(
                    "mma.sync.aligned.m16n8k16.row.col.f32.f16.f16.f32 "
                    "{%0,%1,%2,%3}, {%4,%5,%6,%7}, {%8,%9}, {%0,%1,%2,%3};"
                    : "+f"(acc[nt][0]), "+f"(acc[nt][1]),
                      "+f"(acc[nt][2]), "+f"(acc[nt][3])
                    : "r"(a0), "r"(a1), "r"(a2), "r"(a3), "r"(bv.x), "r"(bv.y));
            }
            // row-sum mma: B = ones -> accR[0] = rs(r1), accR[2] = rs(r2)
            asm volatile(
                "mma.sync.aligned.m16n8k16.row.col.f32.f16.f16.f32 "
                "{%0,%1,%2,%3}, {%4,%5,%6,%7}, {%8,%9}, {%0,%1,%2,%3};"
                : "+f"(accR[0]), "+f"(accR[1]), "+f"(accR[2]), "+f"(accR[3])
                : "r"(a0), "r"(a1), "r"(a2), "r"(a3), "r"(ONES), "r"(ONES));
        }

        if (jt < 31) {
            if (tid < 128) s_sdst[(jt + 1) & 1][tid] = sd_r;
            smask[(jt + 1) & 1][srow * 4 + sq]     = mA;
            smask[(jt + 1) & 1][srow * 4 + 2 + sq] = mB;
        }
    }

    float inv1 = 1.0f / accR[0], inv2 = 1.0f / accR[2];

    float* o1 = g_attn + (size_t)(head * NN + ibase + r1) * FOUT + 2 * t;
    float* o2 = g_attn + (size_t)(head * NN + ibase + r2) * FOUT + 2 * t;
    #pragma unroll
    for (int nt = 0; nt < 8; nt++) {
        float2 v1; v1.x = acc[nt][0] * inv1; v1.y = acc[nt][1] * inv1;
        float2 v2; v2.x = acc[nt][2] * inv2; v2.y = acc[nt][3] * inv2;
        *(float2*)(o1 + nt * 8) = v1;
        *(float2*)(o2 + nt * 8) = v2;
    }
}

// ---------------- finalize: mean over heads (+ skip), LeakyReLU -----------
__global__ void k_final(float* __restrict__ out) {
    int idx = blockIdx.x * 256 + threadIdx.x;
    int i = idx >> 6, o = idx & 63;
    float s = 0.f;
    #pragma unroll
    for (int h = 0; h < NH; h++)
        s += g_attn[(h * NN + i) * FOUT + o] + g_hs[i * CT + 512 + h * 64 + o];
    s *= 0.125f;
    out[idx] = fmaxf(s, SLOPE * s);
}

// ---------------- launch ---------------------------------------------------
extern "C" void kernel_launch(void* const* d_in, const int* in_sizes, int n_in,
                              void* d_out, int out_size) {
    const float* x    = (const float*)d_in[0];   // [4096,128]
    const float* topo = (const float*)d_in[1];   // [4096,4096]
    const float* proj = (const float*)d_in[2];   // [8,128,64]
    const float* wsrc = (const float*)d_in[3];   // [8,64]
    const float* wdst = (const float*)d_in[4];   // [8,64]
    const float* skw  = (const float*)d_in[5];   // [512,128]
    float* out = (float*)d_out;                  // [4096,64]

    k_pack_w<<<512, 256>>>(proj, skw);
    k_mask<<<16384, 256>>>(topo);
    k_gemm<<<dim3(32, 8), 256>>>(x);
    k_svec<<<4096, 256>>>(wsrc, wdst);
    k_transp<<<dim3(128, 2, 8), dim3(32, 8)>>>();
    k_attn<<<dim3(32, 8), 256>>>();
    k_final<<<1024, 256>>>(out);
}

// round 14
// speedup vs baseline: 2.4016x; 1.0153x over previous
#include <cuda_runtime.h>
#include <cuda_fp16.h>
#include <cstdint>

#define NN   4096
#define FIN  128
#define FOUT 64
#define NH   8
#define CT   1024
#define SLOPE 0.2f
#define BS_H 144   // halves per B smem row: 128 data + 16 pad (word-stride 72 ≡ 8 mod 32)
#define LOG2E 1.4426950408889634f

// ---------------- scratch (device globals; no allocations) ----------------
__device__ float    g_Wt[CT * FIN];           // packed weights [1024 c][128 k], tf32-rounded
__device__ float    g_hs[NN * CT];            // [n][1024]: 0..511 h per head, 512..1023 skip
__device__ __half   g_hH[NH * FOUT * NN];     // [h][o][j], f16, j 16-groups frag-permuted
__device__ float    g_ssrc[NH * NN];          // pre-scaled by log2(e)
__device__ float    g_sdst[NH * NN];          // pre-scaled by log2(e)
__device__ unsigned g_maskT[(NN / 32) * NN];  // [word w][i] transposed adjacency bitmask
__device__ float    g_attnP[2][NH * NN * FOUT]; // per-j-half unnormalized partials
__device__ float    g_rsP[2][NH * NN];          // per-j-half partial row sums

__device__ __forceinline__ uint32_t smem_u32(const void* p) {
    uint32_t a;
    asm("{ .reg .u64 t; cvta.to.shared.u64 t, %1; cvt.u32.u64 %0, t; }" : "=r"(a) : "l"(p));
    return a;
}

__device__ __forceinline__ float rndtf32(float v) {
    uint32_t u;
    asm("cvt.rna.tf32.f32 %0, %1;" : "=r"(u) : "f"(v));
    return __uint_as_float(u);
}

// ---------------- pack proj + skip_w^T (transposed, tf32-rounded) ---------
__global__ void k_pack_w(const float* __restrict__ proj, const float* __restrict__ skw) {
    int idx = blockIdx.x * 256 + threadIdx.x;   // 0..131071
    int c = idx >> 7, k = idx & 127;
    float v = (c < 512) ? proj[(c >> 6) * (FIN * FOUT) + k * FOUT + (c & 63)]
                        : skw[(c - 512) * FIN + k];
    g_Wt[idx] = rndtf32(v);
}

// ---------------- adjacency bitmask (transposed: [word][i]) ---------------
__global__ void k_mask(const float* __restrict__ topo) {
    int wt = blockIdx.x * 8 + (threadIdx.x >> 5);   // 0..131071
    int lane = threadIdx.x & 31;
    int i = wt >> 5, w4 = (wt & 31) * 4;
    const float* row = topo + (size_t)i * NN + w4 * 32;
    unsigned b0 = __ballot_sync(0xffffffffu, row[lane]      > -1e8f);
    unsigned b1 = __ballot_sync(0xffffffffu, row[32 + lane] > -1e8f);
    unsigned b2 = __ballot_sync(0xffffffffu, row[64 + lane] > -1e8f);
    unsigned b3 = __ballot_sync(0xffffffffu, row[96 + lane] > -1e8f);
    if (lane < 4) {
        unsigned bb = (lane == 0) ? b0 : (lane == 1) ? b1 : (lane == 2) ? b2 : b3;
        g_maskT[(w4 + lane) * NN + i] = bb;
    }
}

// ---------------- GEMM (tf32 tensor cores): g_hs = x @ Wt^T ---------------
__global__ void __launch_bounds__(256) k_gemm(const float* __restrict__ x) {
    __shared__ float sA[128][36];
    __shared__ float sB[128][36];
    int tid = threadIdx.x, lane = tid & 31, wid = tid >> 5;
    int g = lane >> 2, t = lane & 3;
    int bm = blockIdx.x, bn = blockIdx.y;
    int wm = (wid & 1) * 64, wn = (wid >> 1) * 32;

    float acc[4][4][4];
    #pragma unroll
    for (int mf = 0; mf < 4; mf++)
        #pragma unroll
        for (int nf = 0; nf < 4; nf++)
            acc[mf][nf][0] = acc[mf][nf][1] = acc[mf][nf][2] = acc[mf][nf][3] = 0.f;

    for (int kc = 0; kc < 4; kc++) {
        __syncthreads();
        #pragma unroll
        for (int it = 0; it < 4; it++) {
            int idx = tid + it * 256;
            int r = idx >> 3, kq = idx & 7;
            float4 v = *(const float4*)(x + (size_t)(bm * 128 + r) * FIN + kc * 32 + kq * 4);
            sA[r][kq * 4 + 0] = rndtf32(v.x);
            sA[r][kq * 4 + 1] = rndtf32(v.y);
            sA[r][kq * 4 + 2] = rndtf32(v.z);
            sA[r][kq * 4 + 3] = rndtf32(v.w);
            float4 w = *(const float4*)(g_Wt + (size_t)(bn * 128 + r) * FIN + kc * 32 + kq * 4);
            *(float4*)(&sB[r][kq * 4]) = w;
        }
        __syncthreads();
        #pragma unroll
        for (int ks = 0; ks < 4; ks++) {
            int kk = ks * 8;
            uint32_t a[4][4], b[4][2];
            #pragma unroll
            for (int mf = 0; mf < 4; mf++) {
                a[mf][0] = __float_as_uint(sA[wm + mf * 16 + g][kk + t]);
                a[mf][1] = __float_as_uint(sA[wm + mf * 16 + 8 + g][kk + t]);
                a[mf][2] = __float_as_uint(sA[wm + mf * 16 + g][kk + 4 + t]);
                a[mf][3] = __float_as_uint(sA[wm + mf * 16 + 8 + g][kk + 4 + t]);
            }
            #pragma unroll
            for (int nf = 0; nf < 4; nf++) {
                b[nf][0] = __float_as_uint(sB[wn + nf * 8 + g][kk + t]);
                b[nf][1] = __float_as_uint(sB[wn + nf * 8 + g][kk + 4 + t]);
            }
            #pragma unroll
            for (int mf = 0; mf < 4; mf++)
                #pragma unroll
                for (int nf = 0; nf < 4; nf++)
                    asm volatile(
                        "mma.sync.aligned.m16n8k8.row.col.f32.tf32.tf32.f32 "
                        "{%0,%1,%2,%3}, {%4,%5,%6,%7}, {%8,%9}, {%0,%1,%2,%3};"
                        : "+f"(acc[mf][nf][0]), "+f"(acc[mf][nf][1]),
                          "+f"(acc[mf][nf][2]), "+f"(acc[mf][nf][3])
                        : "r"(a[mf][0]), "r"(a[mf][1]), "r"(a[mf][2]), "r"(a[mf][3]),
                          "r"(b[nf][0]), "r"(b[nf][1]));
        }
    }

    #pragma unroll
    for (int mf = 0; mf < 4; mf++)
        #pragma unroll
        for (int nf = 0; nf < 4; nf++) {
            int m = bm * 128 + wm + mf * 16;
            int col = bn * 128 + wn + nf * 8 + 2 * t;
            float2 v0; v0.x = acc[mf][nf][0]; v0.y = acc[mf][nf][1];
            float2 v1; v1.x = acc[mf][nf][2]; v1.y = acc[mf][nf][3];
            *(float2*)(g_hs + (size_t)(m + g) * CT + col)     = v0;
            *(float2*)(g_hs + (size_t)(m + 8 + g) * CT + col) = v1;
        }
}

// fragment-gather permutation within each 16-j group:
__device__ __forceinline__ int fragperm(int k) {
    return (k < 8) ? ((k >> 1) * 4 + (k & 1))
                   : (((k - 8) >> 1) * 4 + 2 + (k & 1));
}

// ------- fused transpose (h -> f16 frag-permuted hH) + s_src/s_dst --------
// grid (128 j-tiles, 8 heads), block 256 = (32 j, 8 o-groups).
__global__ void k_transp(const float* __restrict__ wsrc, const float* __restrict__ wdst) {
    __shared__ float s[32][68];       // [j][o], pad 68 (float4-aligned rows)
    __shared__ float sw[64], swd[64];
    __shared__ float red[2][8][32];
    int jt = blockIdx.x, h = blockIdx.y;
    int tid = threadIdx.x;
    int x = tid & 31, y = tid >> 5;

    if (tid < 64)  sw[tid]       = wsrc[h * 64 + tid];
    else if (tid < 128) swd[tid - 64] = wdst[h * 64 + tid - 64];
    #pragma unroll
    for (int it = 0; it < 2; it++) {
        int fi = tid + it * 256;      // 512: 32 j-rows x 16 float4
        int j = fi >> 4, q = fi & 15;
        float4 v = *(const float4*)(g_hs + (size_t)(jt * 32 + j) * CT + h * 64 + q * 4);
        *(float4*)(&s[j][q * 4]) = v;
    }
    __syncthreads();

    // f16 transposed store (frag-permuted j)
    int jp = jt * 32 + (x >> 4) * 16 + fragperm(x & 15);
    #pragma unroll
    for (int r = 0; r < 8; r++) {
        int o = y + r * 8;
        g_hH[(h * 64 + o) * NN + jp] = __float2half_rn(s[x][o]);
    }

    // partial dots: thread (x,y) covers node x, o in [y*8, y*8+8)
    float pss = 0.f, psd = 0.f;
    #pragma unroll
    for (int c = 0; c < 8; c++) {
        float v = s[x][y * 8 + c];
        pss += v * sw[y * 8 + c];
        psd += v * swd[y * 8 + c];
    }
    red[0][y][x] = pss;
    red[1][y][x] = psd;
    __syncthreads();
    if (tid < 32) {
        float a = 0.f, b = 0.f;
        #pragma unroll
        for (int yy = 0; yy < 8; yy++) { a += red[0][yy][tid]; b += red[1][yy][tid]; }
        g_ssrc[h * NN + jt * 32 + tid] = a * LOG2E;
        g_sdst[h * NN + jt * 32 + tid] = b * LOG2E;
    }
}

// ---------------- B tile loader: g_hH[64 o][128 j'] -> smem (stride 144) --
__device__ __forceinline__ void load_btile(const __half* __restrict__ hH, int jt,
                                           uint32_t bufb, int tid) {
    #pragma unroll
    for (int c = 0; c < 4; c++) {
        int idx = tid + c * 256;             // 1024 chunks: 64 rows x 16 x 16B
        int o = idx >> 4, ck = idx & 15;
        uint32_t dst = bufb + (uint32_t)(o * (BS_H * 2) + ck * 16);
        const __half* src = hH + o * NN + jt * 128 + ck * 8;
        asm volatile("cp.async.cg.shared.global [%0], [%1], 16;"
                     :: "r"(dst), "l"(src) : "memory");
    }
}

__device__ __forceinline__ uint32_t pack_h2(float lo, float hi) {
    uint32_t u;
    asm("cvt.rn.f16x2.f32 %0, %1, %2;" : "=r"(u) : "f"(hi), "f"(lo));
    return u;
}

// masked leaky + paired f16x2 exp2 (inputs pre-scaled by log2e)
__device__ __forceinline__ uint32_t pgen2(float ssrc, float2 sd, unsigned m, int sh) {
    float v0 = ssrc + sd.x;
    float v1 = ssrc + sd.y;
    v0 = fmaxf(v0, SLOPE * v0);
    v1 = fmaxf(v1, SLOPE * v1);
    v0 = ((m >> sh) & 1u) ? v0 : -1e5f;
    v1 = ((m >> (sh + 1)) & 1u) ? v1 : -1e5f;
    uint32_t pk = pack_h2(v0, v1);
    uint32_t e;
    asm("ex2.approx.f16x2 %0, %1;" : "=r"(e) : "r"(pk));
    return e;
}

// ---------------- main attention: P-gen + P@h via mma.sync f16 ------------
// grid (32 i-tiles, 8 heads, 2 j-halves), block 256 = 8 warps; warp owns 16 rows.
// Writes unnormalized partials + partial row-sums (combined in k_final).
__global__ void __launch_bounds__(256, 3) k_attn() {
    __shared__ __half   sB[2][64 * BS_H];   // 2 x 18432 B
    __shared__ float    s_sdst[2][128];
    __shared__ unsigned smask[2][128 * 4];  // [row r][word q]

    int tid = threadIdx.x, lane = tid & 31, wid = tid >> 5;
    int g = lane >> 2, t = lane & 3;
    int head = blockIdx.y, ibase = blockIdx.x * 128;
    int jh = blockIdx.z, jt0 = jh * 16;
    int r1 = wid * 16 + g, r2 = r1 + 8;
    int srow = tid & 127, sq = tid >> 7;

    float ssr1 = g_ssrc[head * NN + ibase + r1];
    float ssr2 = g_ssrc[head * NN + ibase + r2];
    const __half* hH = g_hH + (size_t)head * (FOUT * NN);
    uint32_t sb0 = smem_u32(sB);
    const uint32_t ONES = 0x3C003C00u;      // (1.0h, 1.0h)

    float acc[8][4], accR[4];
    #pragma unroll
    for (int nt = 0; nt < 8; nt++)
        acc[nt][0] = acc[nt][1] = acc[nt][2] = acc[nt][3] = 0.f;
    accR[0] = accR[1] = accR[2] = accR[3] = 0.f;

    // prologue: stage jt0 (regs -> smem buf 0), start B(jt0)
    float    sd_r = (tid < 128) ? g_sdst[head * NN + jt0 * 128 + tid] : 0.f;
    unsigned mA = g_maskT[(jt0 * 4 + sq) * NN + ibase + srow];
    unsigned mB = g_maskT[(jt0 * 4 + 2 + sq) * NN + ibase + srow];
    if (tid < 128) s_sdst[0][tid] = sd_r;
    smask[0][srow * 4 + sq]     = mA;
    smask[0][srow * 4 + 2 + sq] = mB;
    load_btile(hH, jt0, sb0, tid);
    asm volatile("cp.async.commit_group;" ::: "memory");

    for (int jt = jt0; jt < jt0 + 16; jt++) {
        if (jt < jt0 + 15) {
            if (tid < 128) sd_r = g_sdst[head * NN + (jt + 1) * 128 + tid];
            mA = g_maskT[((jt + 1) * 4 + sq) * NN + ibase + srow];
            mB = g_maskT[((jt + 1) * 4 + 2 + sq) * NN + ibase + srow];
        }

        asm volatile("cp.async.wait_group 0;" ::: "memory");
        __syncthreads();

        if (jt < jt0 + 15) {
            load_btile(hH, jt + 1, sb0 + (uint32_t)(((jt + 1) & 1) * (64 * BS_H * 2)), tid);
            asm volatile("cp.async.commit_group;" ::: "memory");
        }

        const __half*   buf = sB[jt & 1];
        const float*    sds = s_sdst[jt & 1];
        const unsigned* msk = smask[jt & 1];

        #pragma unroll
        for (int c = 0; c < 8; c++) {
            int kb = c * 16;
            float2 sdA = *(const float2*)(sds + kb + 2 * t);
            float2 sdB = *(const float2*)(sds + kb + 2 * t + 8);
            unsigned m1 = msk[r1 * 4 + (c >> 1)];
            unsigned m2 = msk[r2 * 4 + (c >> 1)];
            int sb = (c & 1) * 16 + 2 * t;

            uint32_t a0 = pgen2(ssr1, sdA, m1, sb);
            uint32_t a1 = pgen2(ssr2, sdA, m2, sb);
            uint32_t a2 = pgen2(ssr1, sdB, m1, sb + 8);
            uint32_t a3 = pgen2(ssr2, sdB, m2, sb + 8);

            const __half* bp = buf + g * BS_H + kb + 4 * t;
            #pragma unroll
            for (int nt = 0; nt < 8; nt++) {
                uint2 bv = *(const uint2*)(bp + nt * (8 * BS_H));
                asm volatile(
                    "mma.sync.aligned.m16n8k16.row.col.f32.f16.f16.f32 "
                    "{%0,%1,%2,%3}, {%4,%5,%6,%7}, {%8,%9}, {%0,%1,%2,%3};"
                    : "+f"(acc[nt][0]), "+f"(acc[nt][1]),
                      "+f"(acc[nt][2]), "+f"(acc[nt][3])
                    : "r"(a0), "r"(a1), "r"(a2), "r"(a3), "r"(bv.x), "r"(bv.y));
            }
            asm volatile(
                "mma.sync.aligned.m16n8k16.row.col.f32.f16.f16.f32 "
                "{%0,%1,%2,%3}, {%4,%5,%6,%7}, {%8,%9}, {%0,%1,%2,%3};"
                : "+f"(accR[0]), "+f"(accR[1]), "+f"(accR[2]), "+f"(accR[3])
                : "r"(a0), "r"(a1), "r"(a2), "r"(a3), "r"(ONES), "r"(ONES));
        }

        if (jt < jt0 + 15) {
            if (tid < 128) s_sdst[(jt + 1) & 1][tid] = sd_r;
            smask[(jt + 1) & 1][srow * 4 + sq]     = mA;
            smask[(jt + 1) & 1][srow * 4 + 2 + sq] = mB;
        }
    }

    // store unnormalized partials + partial row-sums
    float* o1 = g_attnP[jh] + (size_t)(head * NN + ibase + r1) * FOUT + 2 * t;
    float* o2 = g_attnP[jh] + (size_t)(head * NN + ibase + r2) * FOUT + 2 * t;
    #pragma unroll
    for (int nt = 0; nt < 8; nt++) {
        float2 v1; v1.x = acc[nt][0]; v1.y = acc[nt][1];
        float2 v2; v2.x = acc[nt][2]; v2.y = acc[nt][3];
        *(float2*)(o1 + nt * 8) = v1;
        *(float2*)(o2 + nt * 8) = v2;
    }
    if (t == 0) {   // accR[0]/accR[2] identical across n-cols (B = ones)
        g_rsP[jh][head * NN + ibase + r1] = accR[0];
        g_rsP[jh][head * NN + ibase + r2] = accR[2];
    }
}

// -------- finalize: combine j-halves, mean over heads (+ skip), LeakyReLU --
__global__ void k_final(float* __restrict__ out) {
    __shared__ float s_inv[32];     // [i-sub][head]
    int ib = blockIdx.x * 4;
    int tid = threadIdx.x;
    if (tid < 32) {
        int ii = tid >> 3, h = tid & 7;
        float r = g_rsP[0][h * NN + ib + ii] + g_rsP[1][h * NN + ib + ii];
        s_inv[tid] = 1.0f / r;
    }
    __syncthreads();
    int ii = tid >> 6, o = tid & 63;
    int i = ib + ii;
    float s = 0.f;
    #pragma unroll
    for (int h = 0; h < NH; h++) {
        float a = g_attnP[0][(size_t)(h * NN + i) * FOUT + o]
                + g_attnP[1][(size_t)(h * NN + i) * FOUT + o];
        s += a * s_inv[ii * 8 + h] + g_hs[(size_t)i * CT + 512 + h * 64 + o];
    }
    s *= 0.125f;
    out[blockIdx.x * 256 + tid] = fmaxf(s, SLOPE * s);
}

// ---------------- launch ---------------------------------------------------
extern "C" void kernel_launch(void* const* d_in, const int* in_sizes, int n_in,
                              void* d_out, int out_size) {
    const float* x    = (const float*)d_in[0];   // [4096,128]
    const float* topo = (const float*)d_in[1];   // [4096,4096]
    const float* proj = (const float*)d_in[2];   // [8,128,64]
    const float* wsrc = (const float*)d_in[3];   // [8,64]
    const float* wdst = (const float*)d_in[4];   // [8,64]
    const float* skw  = (const float*)d_in[5];   // [512,128]
    float* out = (float*)d_out;                  // [4096,64]

    k_pack_w<<<512, 256>>>(proj, skw);
    k_mask<<<16384, 256>>>(topo);
    k_gemm<<<dim3(32, 8), 256>>>(x);
    k_transp<<<dim3(128, 8), 256>>>(wsrc, wdst);
    k_attn<<<dim3(32, 8, 2), 256>>>();
    k_final<<<1024, 256>>>(out);
}